// round 3
// baseline (speedup 1.0000x reference)
#include <cuda_runtime.h>
#include <math.h>

#define NB 16
#define NN 64
#define VOL (NN*NN*NN)      // 262144
#define TOT (NB*VOL)        // 4194304
#define PITCH 65
#define FPITCH 68
#define PI_F 3.14159265358979323846f

// ---------------- scratch (device globals; no allocs allowed) ----------------
static __device__ float2 g_FX[TOT];
static __device__ float2 g_FY[TOT];
static __device__ float  g_AM[NB][12];
static __device__ float  g_AX[NB][12];

// ---------------- complex helpers ----------------
__device__ __forceinline__ float2 cmul(float2 a, float2 b) {
    return make_float2(a.x * b.x - a.y * b.y, a.x * b.y + a.y * b.x);
}

// ---------------- register FFT-8 (natural in / natural out) ----------------
template <bool INV>
__device__ __forceinline__ void fft8(float2* v) {
    float2 t;
    t = v[1]; v[1] = v[4]; v[4] = t;
    t = v[3]; v[3] = v[6]; v[6] = t;
#pragma unroll
    for (int g = 0; g < 8; g += 2) {
        t = v[g + 1];
        v[g + 1] = make_float2(v[g].x - t.x, v[g].y - t.y);
        v[g]     = make_float2(v[g].x + t.x, v[g].y + t.y);
    }
#pragma unroll
    for (int g = 0; g < 8; g += 4) {
        t = v[g + 2];
        v[g + 2] = make_float2(v[g].x - t.x, v[g].y - t.y);
        v[g]     = make_float2(v[g].x + t.x, v[g].y + t.y);
        float2 u = v[g + 3];
        float2 w = INV ? make_float2(-u.y, u.x) : make_float2(u.y, -u.x);
        v[g + 3] = make_float2(v[g + 1].x - w.x, v[g + 1].y - w.y);
        v[g + 1] = make_float2(v[g + 1].x + w.x, v[g + 1].y + w.y);
    }
    const float r = 0.70710678118654752f;
    const float2 w1 = INV ? make_float2(r, r)     : make_float2(r, -r);
    const float2 w2 = INV ? make_float2(0.f, 1.f) : make_float2(0.f, -1.f);
    const float2 w3 = INV ? make_float2(-r, r)    : make_float2(-r, -r);
    t = v[4];
    v[4] = make_float2(v[0].x - t.x, v[0].y - t.y);
    v[0] = make_float2(v[0].x + t.x, v[0].y + t.y);
    t = cmul(v[5], w1);
    v[5] = make_float2(v[1].x - t.x, v[1].y - t.y);
    v[1] = make_float2(v[1].x + t.x, v[1].y + t.y);
    t = cmul(v[6], w2);
    v[6] = make_float2(v[2].x - t.x, v[2].y - t.y);
    v[2] = make_float2(v[2].x + t.x, v[2].y + t.y);
    t = cmul(v[7], w3);
    v[7] = make_float2(v[3].x - t.x, v[3].y - t.y);
    v[3] = make_float2(v[3].x + t.x, v[3].y + t.y);
}

template <bool INV>
__device__ __forceinline__ void twiddle64(float2* v, int j) {
    float s, c;
    sincospif((INV ? 1.0f : -1.0f) * (float)j * (1.0f / 32.0f), &s, &c);
    float2 w = make_float2(c, s), wk = w;
#pragma unroll
    for (int k = 1; k < 8; k++) {
        v[k] = cmul(v[k], wk);
        wk = cmul(wk, w);
    }
}

// 64-pt FFT of one line; exchange via slot region, warp-local sync only.
template <bool INV>
__device__ __forceinline__ void fft64_line(float2* slot, int st, int j, float2* v) {
    fft8<INV>(v);
    twiddle64<INV>(v, j);
    __syncwarp();
#pragma unroll
    for (int k = 0; k < 8; k++) slot[(8 * j + ((k + j) & 7)) * st] = v[k];
    __syncwarp();
#pragma unroll
    for (int n = 0; n < 8; n++) v[n] = slot[(8 * n + ((j + n) & 7)) * st];
    __syncwarp();
    fft8<INV>(v);
}

// stride-9 conflict-free scratch variant (72 float2 per 8-thread group)
template <bool INV>
__device__ __forceinline__ void fft64_scr(float2* S, int j, float2* v) {
    fft8<INV>(v);
    twiddle64<INV>(v, j);
    __syncwarp();
#pragma unroll
    for (int k = 0; k < 8; k++) S[9 * j + k] = v[k];
    __syncwarp();
#pragma unroll
    for (int n = 0; n < 8; n++) v[n] = S[9 * n + j];
    __syncwarp();
    fft8<INV>(v);
}

// ---------------- affine matrix setup ----------------
__device__ void fill_affine(float* A, const float th[6], bool zero_t) {
    const float a0 = th[0] * (2.0f * PI_F) - PI_F;
    const float a1 = th[1] * (2.0f * PI_F) - PI_F;
    const float a2 = th[2] * (2.0f * PI_F) - PI_F;
    float c1, s1, c2, s2, c3, s3;
    sincosf(a0, &s1, &c1);
    sincosf(a1, &s2, &c2);
    sincosf(a2, &s3, &c3);
    float M[9];
    M[0] = c1 * c2 * c3 - s1 * s3;  M[1] = -c1 * c2 * s3 - s1 * c3;  M[2] = c1 * s2;
    M[3] = s1 * c2 * c3 + c1 * s3;  M[4] = -s1 * c2 * s3 + c1 * c3;  M[5] = s1 * s2;
    M[6] = -s2 * c3;                M[7] = s2 * s3;                  M[8] = c2;
    float R[9] = { M[0], M[3], M[6],
                   M[1], M[4], M[7],
                   M[2], M[5], M[8] };
    float loc[3] = {0.f, 0.f, 0.f};
    if (!zero_t) {
        loc[0] = th[3] * 2.0f - 1.0f;
        loc[1] = th[4] * 2.0f - 1.0f;
        loc[2] = th[5] * 2.0f - 1.0f;
    }
#pragma unroll
    for (int i = 0; i < 9; i++) A[i] = R[i];
#pragma unroll
    for (int i = 0; i < 3; i++)
        A[9 + i] = -(R[3 * i] * loc[0] + R[3 * i + 1] * loc[1] + R[3 * i + 2] * loc[2]);
}

__global__ void k_setup(const float* __restrict__ theta) {
    int b = threadIdx.x;
    if (b >= NB) return;
    float th[6];
#pragma unroll
    for (int i = 0; i < 6; i++) th[i] = theta[b * 6 + i];
    fill_affine(g_AM[b], th, true);
    float thr[6];
    const float sc = 64.0f / 66.0f;
#pragma unroll
    for (int i = 0; i < 3; i++) thr[i] = th[i];
#pragma unroll
    for (int i = 3; i < 6; i++) thr[i] = (th[i] - 0.5f) * sc + 0.5f;
    fill_affine(g_AX[b], thr, false);
}

// ---------------- K1: warp BOTH masks (shared coords) -> d_out[TOT..3TOT) ----
__global__ void k_warp_masks(const float* __restrict__ m1, const float* __restrict__ m2,
                             float* __restrict__ out) {
    const int e = blockIdx.x * 256 + threadIdx.x;
    const int b = e >> 18;
    const int rem = e & (VOL - 1);
    const int i = rem >> 12, j = (rem >> 6) & 63, k = rem & 63;
    const float* A = g_AM[b];
    const float gx = (float)i * (2.0f / 63.0f) - 1.0f;
    const float gy = (float)j * (2.0f / 63.0f) - 1.0f;
    const float gz = (float)k * (2.0f / 63.0f) - 1.0f;

    float t0 = A[0] * gx + A[1] * gy + A[2] * gz + A[9];
    float t1 = A[3] * gx + A[4] * gy + A[5] * gz + A[10];
    float t2 = A[6] * gx + A[7] * gy + A[8] * gz + A[11];
    float px = (t0 + 1.0f) * 31.5f;
    float py = (t1 + 1.0f) * 31.5f;
    float pz = (t2 + 1.0f) * 31.5f;
    float fx0 = fminf(fmaxf(floorf(px), 0.f), 63.f);
    float fy0 = fminf(fmaxf(floorf(py), 0.f), 63.f);
    float fz0 = fminf(fmaxf(floorf(pz), 0.f), 63.f);
    int x0 = (int)fx0, y0 = (int)fy0, z0 = (int)fz0;
    int x1 = min(x0 + 1, 63), y1 = min(y0 + 1, 63), z1 = min(z0 + 1, 63);
    float dx = px - fx0, dy = py - fy0, dz = pz - fz0;

    const int i00 = (x0 * 64 + y0) * 64, i01 = (x0 * 64 + y1) * 64;
    const int i10 = (x1 * 64 + y0) * 64, i11 = (x1 * 64 + y1) * 64;
    const float* p1 = m1 + b * VOL;
    const float* p2 = m2 + b * VOL;

    float a000 = __ldg(p1 + i00 + z0), a001 = __ldg(p1 + i00 + z1);
    float a010 = __ldg(p1 + i01 + z0), a011 = __ldg(p1 + i01 + z1);
    float a100 = __ldg(p1 + i10 + z0), a101 = __ldg(p1 + i10 + z1);
    float a110 = __ldg(p1 + i11 + z0), a111 = __ldg(p1 + i11 + z1);
    float b000 = __ldg(p2 + i00 + z0), b001 = __ldg(p2 + i00 + z1);
    float b010 = __ldg(p2 + i01 + z0), b011 = __ldg(p2 + i01 + z1);
    float b100 = __ldg(p2 + i10 + z0), b101 = __ldg(p2 + i10 + z1);
    float b110 = __ldg(p2 + i11 + z0), b111 = __ldg(p2 + i11 + z1);

    float c00 = a000 + (a001 - a000) * dz;
    float c01 = a010 + (a011 - a010) * dz;
    float c10 = a100 + (a101 - a100) * dz;
    float c11 = a110 + (a111 - a110) * dz;
    float c0 = c00 + (c01 - c00) * dy;
    float c1 = c10 + (c11 - c10) * dy;
    out[TOT + e] = c0 + (c1 - c0) * dx;

    c00 = b000 + (b001 - b000) * dz;
    c01 = b010 + (b011 - b010) * dz;
    c10 = b100 + (b101 - b100) * dz;
    c11 = b110 + (b111 - b110) * dz;
    c0 = c00 + (c01 - c00) * dy;
    c1 = c10 + (c11 - c10) * dy;
    out[2 * TOT + e] = c0 + (c1 - c0) * dx;
}

// ---------------- padded-X sampler ----------------
__device__ __forceinline__ float fetchpad(const float* __restrict__ Xb, int a, int b, int c) {
    if ((unsigned)(a - 1) > 63u || (unsigned)(b - 1) > 63u || (unsigned)(c - 1) > 63u) return 0.f;
    return Xb[((a - 1) * 64 + (b - 1)) * 64 + (c - 1)];
}

__device__ __forceinline__ float sampleX(const float* __restrict__ Xb, const float* A,
                                         float gx, float gy, float gz) {
    float t0 = A[0] * gx + A[1] * gy + A[2] * gz + A[9];
    float t1 = A[3] * gx + A[4] * gy + A[5] * gz + A[10];
    float t2 = A[6] * gx + A[7] * gy + A[8] * gz + A[11];
    float px = (t0 + 1.0f) * 32.5f;
    float py = (t1 + 1.0f) * 32.5f;
    float pz = (t2 + 1.0f) * 32.5f;
    float fx0 = fminf(fmaxf(floorf(px), 0.f), 65.f);
    float fy0 = fminf(fmaxf(floorf(py), 0.f), 65.f);
    float fz0 = fminf(fmaxf(floorf(pz), 0.f), 65.f);
    int x0 = (int)fx0, y0 = (int)fy0, z0 = (int)fz0;
    int x1 = min(x0 + 1, 65), y1 = min(y0 + 1, 65), z1 = min(z0 + 1, 65);
    float dx = px - fx0, dy = py - fy0, dz = pz - fz0;
    float v000 = fetchpad(Xb, x0, y0, z0);
    float v001 = fetchpad(Xb, x0, y0, z1);
    float v010 = fetchpad(Xb, x0, y1, z0);
    float v011 = fetchpad(Xb, x0, y1, z1);
    float v100 = fetchpad(Xb, x1, y0, z0);
    float v101 = fetchpad(Xb, x1, y0, z1);
    float v110 = fetchpad(Xb, x1, y1, z0);
    float v111 = fetchpad(Xb, x1, y1, z1);
    float c00 = v000 + (v001 - v000) * dz;
    float c01 = v010 + (v011 - v010) * dz;
    float c10 = v100 + (v101 - v100) * dz;
    float c11 = v110 + (v111 - v110) * dz;
    float c0 = c00 + (c01 - c00) * dy;
    float c1 = c10 + (c11 - c10) * dy;
    return c0 + (c1 - c0) * dx;
}

// ---------------- K2a: warp(X)+sign + 2D FFT (H first, then W) -> g_FX ------
// Axis order chosen so final registers are X[kh=r][kw=j+8k] -> coalesced store.
__global__ void __launch_bounds__(512) k_fwd_x(const float* __restrict__ X) {
    __shared__ float2 tile[64 * PITCH];
    const int b = blockIdx.x >> 6, d = blockIdx.x & 63;
    const float* A = g_AX[b];
    const float* Xb = X + b * VOL;
    const int r = threadIdx.x >> 3, j = threadIdx.x & 7;
    const float gx = (float)(d + 1) * (2.0f / 65.0f) - 1.0f;
    const float gz = (float)(r + 1) * (2.0f / 65.0f) - 1.0f;   // w = r
    float2 v[8];
#pragma unroll
    for (int m = 0; m < 8; m++) {
        const int h = j + 8 * m;
        const float gy = (float)(h + 1) * (2.0f / 65.0f) - 1.0f;
        float val = sampleX(Xb, A, gx, gy, gz);
        if ((d + h + r) & 1) val = -val;
        v[m] = make_float2(val, 0.f);
    }
    // FFT along H: group owns column w=r, exchange down column
    fft64_line<false>(tile + r, PITCH, j, v);
    __syncwarp();
#pragma unroll
    for (int k = 0; k < 8; k++) tile[(j + 8 * k) * PITCH + r] = v[k];  // [kh][w]
    __syncthreads();
    // FFT along W: group owns row kh=r
#pragma unroll
    for (int m = 0; m < 8; m++) v[m] = tile[r * PITCH + j + 8 * m];
    fft64_line<false>(tile + r * PITCH, 1, j, v);
    float2* dst = g_FX + b * VOL + d * 4096;
#pragma unroll
    for (int k = 0; k < 8; k++) dst[r * 64 + j + 8 * k] = v[k];        // coalesced
}

// ---------------- K2b: sign + 2D FFT(W,H) of Y; tile-routed store -> g_FY ---
__global__ void __launch_bounds__(512) k_fwd_y(const float* __restrict__ Y) {
    __shared__ float2 tile[64 * PITCH];
    const int b = blockIdx.x >> 6, d = blockIdx.x & 63;
    const float* Yb = Y + b * VOL + d * 4096;
    const int r = threadIdx.x >> 3, j = threadIdx.x & 7;
    float2 v[8];
#pragma unroll
    for (int m = 0; m < 8; m++) {
        const int w = j + 8 * m;
        float val = Yb[r * 64 + w];
        if ((d + r + w) & 1) val = -val;
        v[m] = make_float2(val, 0.f);
    }
    fft64_line<false>(tile + r * PITCH, 1, j, v);   // along W, row h=r
    __syncwarp();
#pragma unroll
    for (int k = 0; k < 8; k++) tile[r * PITCH + j + 8 * k] = v[k];    // [h][kw]
    __syncthreads();
#pragma unroll
    for (int m = 0; m < 8; m++) v[m] = tile[(j + 8 * m) * PITCH + r];
    fft64_line<false>(tile + r, PITCH, j, v);       // along H, column kw=r
    __syncwarp();
#pragma unroll
    for (int k = 0; k < 8; k++) tile[(j + 8 * k) * PITCH + r] = v[k];  // [kh][kw]
    __syncthreads();
    float2* dst = g_FY + b * VOL + d * 4096;
    for (int idx = threadIdx.x; idx < 4096; idx += 512)
        dst[idx] = tile[(idx >> 6) * PITCH + (idx & 63)];              // coalesced
}

// ---------------- K3: fused fwd-D(FX), fwd-D(FY), combine, inv-D ------------
__global__ void __launch_bounds__(512, 2) k_mid(const float* __restrict__ outp) {
    __shared__ float2 scr[64 * 72];            // 36864 B exchange scratch
    float* mt = (float*)scr;                   // alias: 2 x 64x65 float mask tiles (33280 B)
    const int b = blockIdx.x >> 6, h = blockIdx.x & 63;
    const int g = threadIdx.x >> 3, j = threadIdx.x & 7;
    float2* S = scr + g * 72;
    const int base = b * VOL + h * 64 + g;     // + d*4096

    float2 a[8], v[8];
#pragma unroll
    for (int m = 0; m < 8; m++) a[m] = g_FX[base + (j + 8 * m) * 4096];
    fft64_scr<false>(S, j, a);                 // FXhat[kd = j+8k]
#pragma unroll
    for (int m = 0; m < 8; m++) v[m] = g_FY[base + (j + 8 * m) * 4096];
    fft64_scr<false>(S, j, v);                 // FYhat[kd = j+8k]
    __syncthreads();                           // scr dead; reuse as mask tiles

    const float* M1 = outp + TOT + b * VOL + h * 64;
    const float* M2 = outp + 2 * TOT + b * VOL + h * 64;
    for (int idx = threadIdx.x; idx < 4096; idx += 512) {
        const int kd = idx >> 6, gg = idx & 63;
        mt[kd * 65 + gg]            = M1[kd * 4096 + gg];   // coalesced 128B
        mt[64 * 65 + kd * 65 + gg]  = M2[kd * 4096 + gg];
    }
    __syncthreads();
#pragma unroll
    for (int k = 0; k < 8; k++) {
        const int kd = j + 8 * k;
        const float m1v = mt[kd * 65 + g];
        const float m2v = mt[64 * 65 + kd * 65 + g];
        const float s = ((kd + h + g) & 1) ? -1.0f : 1.0f;
        v[k] = make_float2((a[k].x * m1v + v[k].x * m2v) * s,
                           (a[k].y * m1v + v[k].y * m2v) * s);
    }
    __syncthreads();                           // mask tiles dead; scr reused
    fft64_scr<true>(S, j, v);                  // inverse along D
#pragma unroll
    for (int k = 0; k < 8; k++) g_FX[base + (j + 8 * k) * 4096] = v[k];
}

// ---------------- K4: inverse FFT along W,H + scale + real -> d_out ---------
__global__ void __launch_bounds__(512) k_inv_hw(float* __restrict__ out) {
    __shared__ float2 tile[64 * PITCH];
    float* ft = (float*)tile;                  // pitch-68 float tile (17408 B), conflict-free
    const int b = blockIdx.x >> 6, d = blockIdx.x & 63;
    const float2* gsl = g_FX + b * VOL + d * 4096;
    const int r = threadIdx.x >> 3, j = threadIdx.x & 7;
    float2 v[8];
#pragma unroll
    for (int m = 0; m < 8; m++) v[m] = gsl[r * 64 + j + 8 * m];
    fft64_line<true>(tile + r * PITCH, 1, j, v);   // inverse along W (row kh=r)
    __syncwarp();
#pragma unroll
    for (int k = 0; k < 8; k++) tile[r * PITCH + j + 8 * k] = v[k];    // [kh][w]
    __syncthreads();
#pragma unroll
    for (int m = 0; m < 8; m++) v[m] = tile[(j + 8 * m) * PITCH + r];
    fft64_line<true>(tile + r, PITCH, j, v);       // inverse along H (col w=r)
    __syncthreads();                               // tile float2 use done
    const float sc = 1.0f / (float)VOL;
#pragma unroll
    for (int k = 0; k < 8; k++) ft[(j + 8 * k) * FPITCH + r] = v[k].x * sc;  // bank-CF
    __syncthreads();
    float4* dst = (float4*)(out + b * VOL + d * 4096);
    for (int q = threadIdx.x; q < 1024; q += 512) {
        const int row = q >> 4, c4 = (q & 15) * 4;
        dst[q] = *(const float4*)&ft[row * FPITCH + c4];               // 128b coalesced
    }
}

// ---------------- launch ----------------
extern "C" void kernel_launch(void* const* d_in, const int* in_sizes, int n_in,
                              void* d_out, int out_size) {
    const float* X     = (const float*)d_in[0];
    const float* Y     = (const float*)d_in[1];
    const float* m1    = (const float*)d_in[2];
    const float* m2    = (const float*)d_in[3];
    const float* theta = (const float*)d_in[4];
    float* out = (float*)d_out;

    k_setup<<<1, 32>>>(theta);
    k_warp_masks<<<TOT / 256, 256>>>(m1, m2, out);
    k_fwd_x<<<NB * 64, 512>>>(X);
    k_fwd_y<<<NB * 64, 512>>>(Y);
    k_mid<<<NB * 64, 512>>>(out);
    k_inv_hw<<<NB * 64, 512>>>(out);
}

// round 4
// speedup vs baseline: 1.2457x; 1.2457x over previous
#include <cuda_runtime.h>
#include <math.h>

#define NB 16
#define NN 64
#define VOL (NN*NN*NN)      // 262144
#define TOT (NB*VOL)        // 4194304
#define P2 65               // float2 tile/scratch pitch
#define PI_F 3.14159265358979323846f

// ---------------- scratch (device globals; no allocs allowed) ----------------
static __device__ float2 g_FX[TOT];
static __device__ float2 g_FY[TOT];
static __device__ float  g_AM[NB][12];
static __device__ float  g_AX[NB][12];

// ---------------- complex helpers ----------------
__device__ __forceinline__ float2 cmul(float2 a, float2 b) {
    return make_float2(a.x * b.x - a.y * b.y, a.x * b.y + a.y * b.x);
}

// ---------------- register FFT-8 (natural in / natural out) ----------------
template <bool INV>
__device__ __forceinline__ void fft8(float2* v) {
    float2 t;
    t = v[1]; v[1] = v[4]; v[4] = t;
    t = v[3]; v[3] = v[6]; v[6] = t;
#pragma unroll
    for (int g = 0; g < 8; g += 2) {
        t = v[g + 1];
        v[g + 1] = make_float2(v[g].x - t.x, v[g].y - t.y);
        v[g]     = make_float2(v[g].x + t.x, v[g].y + t.y);
    }
#pragma unroll
    for (int g = 0; g < 8; g += 4) {
        t = v[g + 2];
        v[g + 2] = make_float2(v[g].x - t.x, v[g].y - t.y);
        v[g]     = make_float2(v[g].x + t.x, v[g].y + t.y);
        float2 u = v[g + 3];
        float2 w = INV ? make_float2(-u.y, u.x) : make_float2(u.y, -u.x);
        v[g + 3] = make_float2(v[g + 1].x - w.x, v[g + 1].y - w.y);
        v[g + 1] = make_float2(v[g + 1].x + w.x, v[g + 1].y + w.y);
    }
    const float r = 0.70710678118654752f;
    const float2 w1 = INV ? make_float2(r, r)     : make_float2(r, -r);
    const float2 w2 = INV ? make_float2(0.f, 1.f) : make_float2(0.f, -1.f);
    const float2 w3 = INV ? make_float2(-r, r)    : make_float2(-r, -r);
    t = v[4];
    v[4] = make_float2(v[0].x - t.x, v[0].y - t.y);
    v[0] = make_float2(v[0].x + t.x, v[0].y + t.y);
    t = cmul(v[5], w1);
    v[5] = make_float2(v[1].x - t.x, v[1].y - t.y);
    v[1] = make_float2(v[1].x + t.x, v[1].y + t.y);
    t = cmul(v[6], w2);
    v[6] = make_float2(v[2].x - t.x, v[2].y - t.y);
    v[2] = make_float2(v[2].x + t.x, v[2].y + t.y);
    t = cmul(v[7], w3);
    v[7] = make_float2(v[3].x - t.x, v[3].y - t.y);
    v[3] = make_float2(v[3].x + t.x, v[3].y + t.y);
}

template <bool INV>
__device__ __forceinline__ void twiddle64(float2* v, int j) {
    float s, c;
    sincospif((INV ? 1.0f : -1.0f) * (float)j * (1.0f / 32.0f), &s, &c);
    float2 w = make_float2(c, s), wk = w;
#pragma unroll
    for (int k = 1; k < 8; k++) {
        v[k] = cmul(v[k], wk);
        wk = cmul(wk, w);
    }
}

// Row-mode 64-pt FFT: 8-thread group inside one warp, slots = rowbase[0..63].
// Input x[j+8m] in v; output X[j+8k] in v.
template <bool INV>
__device__ __forceinline__ void fft64_row(float2* rowbase, int j, float2* v) {
    fft8<INV>(v);
    twiddle64<INV>(v, j);
    __syncwarp();
#pragma unroll
    for (int k = 0; k < 8; k++) rowbase[8 * j + ((k + j) & 7)] = v[k];
    __syncwarp();
#pragma unroll
    for (int n = 0; n < 8; n++) v[n] = rowbase[8 * n + ((j + n) & 7)];
    __syncwarp();
    fft8<INV>(v);
}

// Transposed-mode 64-pt FFT: group lane jj (0..7) spans warps; g = 0..63 is
// the warp-contiguous index. scr is a [slot 0..63][g 0..63] pitch-P2 region.
// All scratch accesses are (const + g) per instruction -> conflict-free.
// NOTE: caller must __syncthreads before reusing scr after this returns.
template <bool INV>
__device__ __forceinline__ void fft64_T(float2* scr, int jj, int g, float2* v) {
    fft8<INV>(v);
    twiddle64<INV>(v, jj);
    __syncthreads();               // also guards any prior use of scr
#pragma unroll
    for (int k = 0; k < 8; k++) scr[(8 * jj + k) * P2 + g] = v[k];
    __syncthreads();
#pragma unroll
    for (int n = 0; n < 8; n++) v[n] = scr[(8 * n + jj) * P2 + g];
    fft8<INV>(v);
}

// ---------------- affine matrix setup ----------------
__device__ void fill_affine(float* A, const float th[6], bool zero_t) {
    const float a0 = th[0] * (2.0f * PI_F) - PI_F;
    const float a1 = th[1] * (2.0f * PI_F) - PI_F;
    const float a2 = th[2] * (2.0f * PI_F) - PI_F;
    float c1, s1, c2, s2, c3, s3;
    sincosf(a0, &s1, &c1);
    sincosf(a1, &s2, &c2);
    sincosf(a2, &s3, &c3);
    float M[9];
    M[0] = c1 * c2 * c3 - s1 * s3;  M[1] = -c1 * c2 * s3 - s1 * c3;  M[2] = c1 * s2;
    M[3] = s1 * c2 * c3 + c1 * s3;  M[4] = -s1 * c2 * s3 + c1 * c3;  M[5] = s1 * s2;
    M[6] = -s2 * c3;                M[7] = s2 * s3;                  M[8] = c2;
    float R[9] = { M[0], M[3], M[6],
                   M[1], M[4], M[7],
                   M[2], M[5], M[8] };
    float loc[3] = {0.f, 0.f, 0.f};
    if (!zero_t) {
        loc[0] = th[3] * 2.0f - 1.0f;
        loc[1] = th[4] * 2.0f - 1.0f;
        loc[2] = th[5] * 2.0f - 1.0f;
    }
#pragma unroll
    for (int i = 0; i < 9; i++) A[i] = R[i];
#pragma unroll
    for (int i = 0; i < 3; i++)
        A[9 + i] = -(R[3 * i] * loc[0] + R[3 * i + 1] * loc[1] + R[3 * i + 2] * loc[2]);
}

__global__ void k_setup(const float* __restrict__ theta) {
    int b = threadIdx.x;
    if (b >= NB) return;
    float th[6];
#pragma unroll
    for (int i = 0; i < 6; i++) th[i] = theta[b * 6 + i];
    fill_affine(g_AM[b], th, true);
    float thr[6];
    const float sc = 64.0f / 66.0f;
#pragma unroll
    for (int i = 0; i < 3; i++) thr[i] = th[i];
#pragma unroll
    for (int i = 3; i < 6; i++) thr[i] = (th[i] - 0.5f) * sc + 0.5f;
    fill_affine(g_AX[b], thr, false);
}

// ---------------- K1: warp BOTH masks -> d_out[TOT..3TOT) ----------------
__global__ void k_warp_masks(const float* __restrict__ m1, const float* __restrict__ m2,
                             float* __restrict__ out) {
    const int e = blockIdx.x * 256 + threadIdx.x;
    const int b = e >> 18;
    const int rem = e & (VOL - 1);
    const int i = rem >> 12, j = (rem >> 6) & 63, k = rem & 63;
    const float* A = g_AM[b];
    const float gx = (float)i * (2.0f / 63.0f) - 1.0f;
    const float gy = (float)j * (2.0f / 63.0f) - 1.0f;
    const float gz = (float)k * (2.0f / 63.0f) - 1.0f;

    float t0 = A[0] * gx + A[1] * gy + A[2] * gz + A[9];
    float t1 = A[3] * gx + A[4] * gy + A[5] * gz + A[10];
    float t2 = A[6] * gx + A[7] * gy + A[8] * gz + A[11];
    float px = (t0 + 1.0f) * 31.5f;
    float py = (t1 + 1.0f) * 31.5f;
    float pz = (t2 + 1.0f) * 31.5f;
    float fx0 = fminf(fmaxf(floorf(px), 0.f), 63.f);
    float fy0 = fminf(fmaxf(floorf(py), 0.f), 63.f);
    float fz0 = fminf(fmaxf(floorf(pz), 0.f), 63.f);
    int x0 = (int)fx0, y0 = (int)fy0, z0 = (int)fz0;
    int x1 = min(x0 + 1, 63), y1 = min(y0 + 1, 63), z1 = min(z0 + 1, 63);
    float dx = px - fx0, dy = py - fy0, dz = pz - fz0;

    const int i00 = (x0 * 64 + y0) * 64, i01 = (x0 * 64 + y1) * 64;
    const int i10 = (x1 * 64 + y0) * 64, i11 = (x1 * 64 + y1) * 64;
    const float* p1 = m1 + b * VOL;
    const float* p2 = m2 + b * VOL;

    float a000 = __ldg(p1 + i00 + z0), a001 = __ldg(p1 + i00 + z1);
    float a010 = __ldg(p1 + i01 + z0), a011 = __ldg(p1 + i01 + z1);
    float a100 = __ldg(p1 + i10 + z0), a101 = __ldg(p1 + i10 + z1);
    float a110 = __ldg(p1 + i11 + z0), a111 = __ldg(p1 + i11 + z1);
    float b000 = __ldg(p2 + i00 + z0), b001 = __ldg(p2 + i00 + z1);
    float b010 = __ldg(p2 + i01 + z0), b011 = __ldg(p2 + i01 + z1);
    float b100 = __ldg(p2 + i10 + z0), b101 = __ldg(p2 + i10 + z1);
    float b110 = __ldg(p2 + i11 + z0), b111 = __ldg(p2 + i11 + z1);

    float c00 = a000 + (a001 - a000) * dz;
    float c01 = a010 + (a011 - a010) * dz;
    float c10 = a100 + (a101 - a100) * dz;
    float c11 = a110 + (a111 - a110) * dz;
    float c0 = c00 + (c01 - c00) * dy;
    float c1 = c10 + (c11 - c10) * dy;
    out[TOT + e] = c0 + (c1 - c0) * dx;

    c00 = b000 + (b001 - b000) * dz;
    c01 = b010 + (b011 - b010) * dz;
    c10 = b100 + (b101 - b100) * dz;
    c11 = b110 + (b111 - b110) * dz;
    c0 = c00 + (c01 - c00) * dy;
    c1 = c10 + (c11 - c10) * dy;
    out[2 * TOT + e] = c0 + (c1 - c0) * dx;
}

// ---------------- padded-X sampler ----------------
__device__ __forceinline__ float fetchpad(const float* __restrict__ Xb, int a, int b, int c) {
    if ((unsigned)(a - 1) > 63u || (unsigned)(b - 1) > 63u || (unsigned)(c - 1) > 63u) return 0.f;
    return Xb[((a - 1) * 64 + (b - 1)) * 64 + (c - 1)];
}

__device__ __forceinline__ float sampleX(const float* __restrict__ Xb, const float* A,
                                         float gx, float gy, float gz) {
    float t0 = A[0] * gx + A[1] * gy + A[2] * gz + A[9];
    float t1 = A[3] * gx + A[4] * gy + A[5] * gz + A[10];
    float t2 = A[6] * gx + A[7] * gy + A[8] * gz + A[11];
    float px = (t0 + 1.0f) * 32.5f;
    float py = (t1 + 1.0f) * 32.5f;
    float pz = (t2 + 1.0f) * 32.5f;
    float fx0 = fminf(fmaxf(floorf(px), 0.f), 65.f);
    float fy0 = fminf(fmaxf(floorf(py), 0.f), 65.f);
    float fz0 = fminf(fmaxf(floorf(pz), 0.f), 65.f);
    int x0 = (int)fx0, y0 = (int)fy0, z0 = (int)fz0;
    int x1 = min(x0 + 1, 65), y1 = min(y0 + 1, 65), z1 = min(z0 + 1, 65);
    float dx = px - fx0, dy = py - fy0, dz = pz - fz0;
    float v000 = fetchpad(Xb, x0, y0, z0);
    float v001 = fetchpad(Xb, x0, y0, z1);
    float v010 = fetchpad(Xb, x0, y1, z0);
    float v011 = fetchpad(Xb, x0, y1, z1);
    float v100 = fetchpad(Xb, x1, y0, z0);
    float v101 = fetchpad(Xb, x1, y0, z1);
    float v110 = fetchpad(Xb, x1, y1, z0);
    float v111 = fetchpad(Xb, x1, y1, z1);
    float c00 = v000 + (v001 - v000) * dz;
    float c01 = v010 + (v011 - v010) * dz;
    float c10 = v100 + (v101 - v100) * dz;
    float c11 = v110 + (v111 - v110) * dz;
    float c0 = c00 + (c01 - c00) * dy;
    float c1 = c10 + (c11 - c10) * dy;
    return c0 + (c1 - c0) * dx;
}

// ====== shared 2D-FFT pipeline (pass1 row/W, pass2 transposed/H) ======
// tile column swizzle: column c of row h stored at (c + 7h)&63  -> CF both ways
__device__ __forceinline__ int swz(int c, int h) { return (c + 7 * h) & 63; }

// ---------------- K2a: warp(X)+sign + 2D FFT(W,H) -> g_FX ----------------
__global__ void __launch_bounds__(512) k_fwd_x(const float* __restrict__ X) {
    __shared__ float2 tile[64 * P2];
    const int b = blockIdx.x >> 6, d = blockIdx.x & 63;
    const float* A = g_AX[b];
    const float* Xb = X + b * VOL;
    const float gx = (float)(d + 1) * (2.0f / 65.0f) - 1.0f;

    // pass 1: row FFT along W. thread (r=row h, j)
    {
        const int r = threadIdx.x >> 3, j = threadIdx.x & 7;
        const float gy = (float)(r + 1) * (2.0f / 65.0f) - 1.0f;
        float2 v[8];
#pragma unroll
        for (int m = 0; m < 8; m++) {
            const int w = j + 8 * m;
            const float gz = (float)(w + 1) * (2.0f / 65.0f) - 1.0f;
            float val = sampleX(Xb, A, gx, gy, gz);
            if ((d + r + w) & 1) val = -val;
            v[m] = make_float2(val, 0.f);
        }
        fft64_row<false>(tile + r * P2, j, v);
#pragma unroll
        for (int k = 0; k < 8; k++) tile[r * P2 + swz(j + 8 * k, r)] = v[k];
    }
    __syncthreads();
    // pass 2: column FFT along H, transposed mapping. thread (g=kw, jj)
    {
        const int g = threadIdx.x & 63, jj = threadIdx.x >> 6;
        float2 v[8];
#pragma unroll
        for (int m = 0; m < 8; m++) {
            const int h = jj + 8 * m;
            v[m] = tile[h * P2 + swz(g, h)];
        }
        fft64_T<false>(tile, jj, g, v);
        float2* dst = g_FX + b * VOL + d * 4096;
#pragma unroll
        for (int k = 0; k < 8; k++) dst[(jj + 8 * k) * 64 + g] = v[k];  // coalesced
    }
}

// ---------------- K2b: sign + 2D FFT(W,H) of Y -> g_FY ----------------
__global__ void __launch_bounds__(512) k_fwd_y(const float* __restrict__ Y) {
    __shared__ float2 tile[64 * P2];
    const int b = blockIdx.x >> 6, d = blockIdx.x & 63;
    const float* Yb = Y + b * VOL + d * 4096;
    {
        const int r = threadIdx.x >> 3, j = threadIdx.x & 7;
        float2 v[8];
#pragma unroll
        for (int m = 0; m < 8; m++) {
            const int w = j + 8 * m;
            float val = Yb[r * 64 + w];
            if ((d + r + w) & 1) val = -val;
            v[m] = make_float2(val, 0.f);
        }
        fft64_row<false>(tile + r * P2, j, v);
#pragma unroll
        for (int k = 0; k < 8; k++) tile[r * P2 + swz(j + 8 * k, r)] = v[k];
    }
    __syncthreads();
    {
        const int g = threadIdx.x & 63, jj = threadIdx.x >> 6;
        float2 v[8];
#pragma unroll
        for (int m = 0; m < 8; m++) {
            const int h = jj + 8 * m;
            v[m] = tile[h * P2 + swz(g, h)];
        }
        fft64_T<false>(tile, jj, g, v);
        float2* dst = g_FY + b * VOL + d * 4096;
#pragma unroll
        for (int k = 0; k < 8; k++) dst[(jj + 8 * k) * 64 + g] = v[k];  // coalesced
    }
}

// ---------------- K3: fused fwd-D(FX), fwd-D(FY), combine, inv-D ------------
// Transposed mapping throughout: all global accesses 256B-contiguous per instr.
__global__ void __launch_bounds__(512, 2) k_mid(const float* __restrict__ outp) {
    __shared__ float2 scr[64 * P2];
    const int b = blockIdx.x >> 6, h = blockIdx.x & 63;
    const int g = threadIdx.x & 63, jj = threadIdx.x >> 6;
    const int base = b * VOL + h * 64 + g;     // + d*4096

    float2 a[8], v[8];
#pragma unroll
    for (int m = 0; m < 8; m++) a[m] = g_FX[base + (jj + 8 * m) * 4096];
    fft64_T<false>(scr, jj, g, a);             // FXhat[kd = jj+8k]
#pragma unroll
    for (int m = 0; m < 8; m++) v[m] = g_FY[base + (jj + 8 * m) * 4096];
    fft64_T<false>(scr, jj, g, v);             // FYhat[kd = jj+8k]

    const float* M1 = outp + TOT;
    const float* M2 = outp + 2 * TOT;
#pragma unroll
    for (int k = 0; k < 8; k++) {
        const int kd = jj + 8 * k;
        const int off = b * VOL + kd * 4096 + h * 64 + g;
        const float m1v = __ldg(M1 + off);     // coalesced 128B
        const float m2v = __ldg(M2 + off);
        const float s = ((kd + h + g) & 1) ? -1.0f : 1.0f;
        v[k] = make_float2((a[k].x * m1v + v[k].x * m2v) * s,
                           (a[k].y * m1v + v[k].y * m2v) * s);
    }
    fft64_T<true>(scr, jj, g, v);              // inverse along D
#pragma unroll
    for (int k = 0; k < 8; k++) g_FX[base + (jj + 8 * k) * 4096] = v[k];  // coalesced
}

// ---------------- K4: inverse FFT along H (transposed) then W + real --------
__global__ void __launch_bounds__(512) k_inv_hw(float* __restrict__ out) {
    __shared__ float2 tile[64 * P2];
    const int b = blockIdx.x >> 6, d = blockIdx.x & 63;
    const float2* gsl = g_FX + b * VOL + d * 4096;
    // pass 1: inverse along H, transposed. thread (g=kw, jj)
    {
        const int g = threadIdx.x & 63, jj = threadIdx.x >> 6;
        float2 v[8];
#pragma unroll
        for (int m = 0; m < 8; m++) v[m] = gsl[(jj + 8 * m) * 64 + g];  // coalesced
        fft64_T<true>(tile, jj, g, v);
        __syncthreads();           // scr readers done before tile reuse
#pragma unroll
        for (int k = 0; k < 8; k++) {
            const int hh = jj + 8 * k;
            tile[hh * P2 + swz(g, hh)] = v[k];
        }
    }
    __syncthreads();
    // pass 2: inverse along W, row mode. thread (r=row h, j)
    {
        const int r = threadIdx.x >> 3, j = threadIdx.x & 7;
        float2 v[8];
#pragma unroll
        for (int m = 0; m < 8; m++) v[m] = tile[r * P2 + swz(j + 8 * m, r)];
        fft64_row<true>(tile + r * P2, j, v);
        float* dst = out + b * VOL + d * 4096 + r * 64;
        const float sc = 1.0f / (float)VOL;
#pragma unroll
        for (int k = 0; k < 8; k++) dst[j + 8 * k] = v[k].x * sc;   // 32B runs
    }
}

// ---------------- launch ----------------
extern "C" void kernel_launch(void* const* d_in, const int* in_sizes, int n_in,
                              void* d_out, int out_size) {
    const float* X     = (const float*)d_in[0];
    const float* Y     = (const float*)d_in[1];
    const float* m1    = (const float*)d_in[2];
    const float* m2    = (const float*)d_in[3];
    const float* theta = (const float*)d_in[4];
    float* out = (float*)d_out;

    k_setup<<<1, 32>>>(theta);
    k_warp_masks<<<TOT / 256, 256>>>(m1, m2, out);
    k_fwd_x<<<NB * 64, 512>>>(X);
    k_fwd_y<<<NB * 64, 512>>>(Y);
    k_mid<<<NB * 64, 512>>>(out);
    k_inv_hw<<<NB * 64, 512>>>(out);
}

// round 5
// speedup vs baseline: 1.2463x; 1.0005x over previous
#include <cuda_runtime.h>
#include <math.h>

#define NB 16
#define NN 64
#define VOL (NN*NN*NN)      // 262144
#define TOT (NB*VOL)        // 4194304
#define P2 65               // float2 tile/scratch pitch
#define PI_F 3.14159265358979323846f

// ---------------- scratch (device globals; no allocs allowed) ----------------
static __device__ float2 g_FX[TOT];
static __device__ float2 g_FY[TOT];
static __device__ float  g_AM[NB][12];
static __device__ float  g_AX[NB][12];

// ---------------- complex helpers ----------------
__device__ __forceinline__ float2 cmul(float2 a, float2 b) {
    return make_float2(a.x * b.x - a.y * b.y, a.x * b.y + a.y * b.x);
}

// ---------------- register FFT-8 (natural in / natural out) ----------------
template <bool INV>
__device__ __forceinline__ void fft8(float2* v) {
    float2 t;
    t = v[1]; v[1] = v[4]; v[4] = t;
    t = v[3]; v[3] = v[6]; v[6] = t;
#pragma unroll
    for (int g = 0; g < 8; g += 2) {
        t = v[g + 1];
        v[g + 1] = make_float2(v[g].x - t.x, v[g].y - t.y);
        v[g]     = make_float2(v[g].x + t.x, v[g].y + t.y);
    }
#pragma unroll
    for (int g = 0; g < 8; g += 4) {
        t = v[g + 2];
        v[g + 2] = make_float2(v[g].x - t.x, v[g].y - t.y);
        v[g]     = make_float2(v[g].x + t.x, v[g].y + t.y);
        float2 u = v[g + 3];
        float2 w = INV ? make_float2(-u.y, u.x) : make_float2(u.y, -u.x);
        v[g + 3] = make_float2(v[g + 1].x - w.x, v[g + 1].y - w.y);
        v[g + 1] = make_float2(v[g + 1].x + w.x, v[g + 1].y + w.y);
    }
    const float r = 0.70710678118654752f;
    const float2 w1 = INV ? make_float2(r, r)     : make_float2(r, -r);
    const float2 w2 = INV ? make_float2(0.f, 1.f) : make_float2(0.f, -1.f);
    const float2 w3 = INV ? make_float2(-r, r)    : make_float2(-r, -r);
    t = v[4];
    v[4] = make_float2(v[0].x - t.x, v[0].y - t.y);
    v[0] = make_float2(v[0].x + t.x, v[0].y + t.y);
    t = cmul(v[5], w1);
    v[5] = make_float2(v[1].x - t.x, v[1].y - t.y);
    v[1] = make_float2(v[1].x + t.x, v[1].y + t.y);
    t = cmul(v[6], w2);
    v[6] = make_float2(v[2].x - t.x, v[2].y - t.y);
    v[2] = make_float2(v[2].x + t.x, v[2].y + t.y);
    t = cmul(v[7], w3);
    v[7] = make_float2(v[3].x - t.x, v[3].y - t.y);
    v[3] = make_float2(v[3].x + t.x, v[3].y + t.y);
}

template <bool INV>
__device__ __forceinline__ void twiddle64(float2* v, int j) {
    float s, c;
    sincospif((INV ? 1.0f : -1.0f) * (float)j * (1.0f / 32.0f), &s, &c);
    float2 w = make_float2(c, s), wk = w;
#pragma unroll
    for (int k = 1; k < 8; k++) {
        v[k] = cmul(v[k], wk);
        wk = cmul(wk, w);
    }
}

// Row-mode 64-pt FFT: 8-thread group inside one warp, slots = rowbase[0..63].
// Input x[j+8m] in v; output X[j+8k] in v.
template <bool INV>
__device__ __forceinline__ void fft64_row(float2* rowbase, int j, float2* v) {
    fft8<INV>(v);
    twiddle64<INV>(v, j);
    __syncwarp();
#pragma unroll
    for (int k = 0; k < 8; k++) rowbase[8 * j + ((k + j) & 7)] = v[k];
    __syncwarp();
#pragma unroll
    for (int n = 0; n < 8; n++) v[n] = rowbase[8 * n + ((j + n) & 7)];
    __syncwarp();
    fft8<INV>(v);
}

// Transposed-mode 64-pt FFT: group lane jj (0..7) spans warps; g = 0..63 is
// the warp-contiguous index. scr is a [slot 0..63][g 0..63] pitch-P2 region.
// All scratch accesses are (const + g) per instruction -> conflict-free.
// NOTE: caller must __syncthreads before reusing scr after this returns.
template <bool INV>
__device__ __forceinline__ void fft64_T(float2* scr, int jj, int g, float2* v) {
    fft8<INV>(v);
    twiddle64<INV>(v, jj);
    __syncthreads();               // also guards any prior use of scr
#pragma unroll
    for (int k = 0; k < 8; k++) scr[(8 * jj + k) * P2 + g] = v[k];
    __syncthreads();
#pragma unroll
    for (int n = 0; n < 8; n++) v[n] = scr[(8 * n + jj) * P2 + g];
    fft8<INV>(v);
}

// ---------------- affine matrix setup ----------------
__device__ void fill_affine(float* A, const float th[6], bool zero_t) {
    const float a0 = th[0] * (2.0f * PI_F) - PI_F;
    const float a1 = th[1] * (2.0f * PI_F) - PI_F;
    const float a2 = th[2] * (2.0f * PI_F) - PI_F;
    float c1, s1, c2, s2, c3, s3;
    sincosf(a0, &s1, &c1);
    sincosf(a1, &s2, &c2);
    sincosf(a2, &s3, &c3);
    float M[9];
    M[0] = c1 * c2 * c3 - s1 * s3;  M[1] = -c1 * c2 * s3 - s1 * c3;  M[2] = c1 * s2;
    M[3] = s1 * c2 * c3 + c1 * s3;  M[4] = -s1 * c2 * s3 + c1 * c3;  M[5] = s1 * s2;
    M[6] = -s2 * c3;                M[7] = s2 * s3;                  M[8] = c2;
    float R[9] = { M[0], M[3], M[6],
                   M[1], M[4], M[7],
                   M[2], M[5], M[8] };
    float loc[3] = {0.f, 0.f, 0.f};
    if (!zero_t) {
        loc[0] = th[3] * 2.0f - 1.0f;
        loc[1] = th[4] * 2.0f - 1.0f;
        loc[2] = th[5] * 2.0f - 1.0f;
    }
#pragma unroll
    for (int i = 0; i < 9; i++) A[i] = R[i];
#pragma unroll
    for (int i = 0; i < 3; i++)
        A[9 + i] = -(R[3 * i] * loc[0] + R[3 * i + 1] * loc[1] + R[3 * i + 2] * loc[2]);
}

__global__ void k_setup(const float* __restrict__ theta) {
    int b = threadIdx.x;
    if (b >= NB) return;
    float th[6];
#pragma unroll
    for (int i = 0; i < 6; i++) th[i] = theta[b * 6 + i];
    fill_affine(g_AM[b], th, true);
    float thr[6];
    const float sc = 64.0f / 66.0f;
#pragma unroll
    for (int i = 0; i < 3; i++) thr[i] = th[i];
#pragma unroll
    for (int i = 3; i < 6; i++) thr[i] = (th[i] - 0.5f) * sc + 0.5f;
    fill_affine(g_AX[b], thr, false);
}

// ---------------- K1: warp BOTH masks -> d_out[TOT..3TOT) ----------------
__global__ void k_warp_masks(const float* __restrict__ m1, const float* __restrict__ m2,
                             float* __restrict__ out) {
    const int e = blockIdx.x * 256 + threadIdx.x;
    const int b = e >> 18;
    const int rem = e & (VOL - 1);
    const int i = rem >> 12, j = (rem >> 6) & 63, k = rem & 63;
    const float* A = g_AM[b];
    const float gx = (float)i * (2.0f / 63.0f) - 1.0f;
    const float gy = (float)j * (2.0f / 63.0f) - 1.0f;
    const float gz = (float)k * (2.0f / 63.0f) - 1.0f;

    float t0 = A[0] * gx + A[1] * gy + A[2] * gz + A[9];
    float t1 = A[3] * gx + A[4] * gy + A[5] * gz + A[10];
    float t2 = A[6] * gx + A[7] * gy + A[8] * gz + A[11];
    float px = (t0 + 1.0f) * 31.5f;
    float py = (t1 + 1.0f) * 31.5f;
    float pz = (t2 + 1.0f) * 31.5f;
    float fx0 = fminf(fmaxf(floorf(px), 0.f), 63.f);
    float fy0 = fminf(fmaxf(floorf(py), 0.f), 63.f);
    float fz0 = fminf(fmaxf(floorf(pz), 0.f), 63.f);
    int x0 = (int)fx0, y0 = (int)fy0, z0 = (int)fz0;
    int x1 = min(x0 + 1, 63), y1 = min(y0 + 1, 63), z1 = min(z0 + 1, 63);
    float dx = px - fx0, dy = py - fy0, dz = pz - fz0;

    const int i00 = (x0 * 64 + y0) * 64, i01 = (x0 * 64 + y1) * 64;
    const int i10 = (x1 * 64 + y0) * 64, i11 = (x1 * 64 + y1) * 64;
    const float* p1 = m1 + b * VOL;
    const float* p2 = m2 + b * VOL;

    float a000 = __ldg(p1 + i00 + z0), a001 = __ldg(p1 + i00 + z1);
    float a010 = __ldg(p1 + i01 + z0), a011 = __ldg(p1 + i01 + z1);
    float a100 = __ldg(p1 + i10 + z0), a101 = __ldg(p1 + i10 + z1);
    float a110 = __ldg(p1 + i11 + z0), a111 = __ldg(p1 + i11 + z1);
    float b000 = __ldg(p2 + i00 + z0), b001 = __ldg(p2 + i00 + z1);
    float b010 = __ldg(p2 + i01 + z0), b011 = __ldg(p2 + i01 + z1);
    float b100 = __ldg(p2 + i10 + z0), b101 = __ldg(p2 + i10 + z1);
    float b110 = __ldg(p2 + i11 + z0), b111 = __ldg(p2 + i11 + z1);

    float c00 = a000 + (a001 - a000) * dz;
    float c01 = a010 + (a011 - a010) * dz;
    float c10 = a100 + (a101 - a100) * dz;
    float c11 = a110 + (a111 - a110) * dz;
    float c0 = c00 + (c01 - c00) * dy;
    float c1 = c10 + (c11 - c10) * dy;
    out[TOT + e] = c0 + (c1 - c0) * dx;

    c00 = b000 + (b001 - b000) * dz;
    c01 = b010 + (b011 - b010) * dz;
    c10 = b100 + (b101 - b100) * dz;
    c11 = b110 + (b111 - b110) * dz;
    c0 = c00 + (c01 - c00) * dy;
    c1 = c10 + (c11 - c10) * dy;
    out[2 * TOT + e] = c0 + (c1 - c0) * dx;
}

// ---------------- padded-X sampler ----------------
__device__ __forceinline__ float fetchpad(const float* __restrict__ Xb, int a, int b, int c) {
    if ((unsigned)(a - 1) > 63u || (unsigned)(b - 1) > 63u || (unsigned)(c - 1) > 63u) return 0.f;
    return Xb[((a - 1) * 64 + (b - 1)) * 64 + (c - 1)];
}

__device__ __forceinline__ float sampleX(const float* __restrict__ Xb, const float* A,
                                         float gx, float gy, float gz) {
    float t0 = A[0] * gx + A[1] * gy + A[2] * gz + A[9];
    float t1 = A[3] * gx + A[4] * gy + A[5] * gz + A[10];
    float t2 = A[6] * gx + A[7] * gy + A[8] * gz + A[11];
    float px = (t0 + 1.0f) * 32.5f;
    float py = (t1 + 1.0f) * 32.5f;
    float pz = (t2 + 1.0f) * 32.5f;
    float fx0 = fminf(fmaxf(floorf(px), 0.f), 65.f);
    float fy0 = fminf(fmaxf(floorf(py), 0.f), 65.f);
    float fz0 = fminf(fmaxf(floorf(pz), 0.f), 65.f);
    int x0 = (int)fx0, y0 = (int)fy0, z0 = (int)fz0;
    int x1 = min(x0 + 1, 65), y1 = min(y0 + 1, 65), z1 = min(z0 + 1, 65);
    float dx = px - fx0, dy = py - fy0, dz = pz - fz0;
    float v000 = fetchpad(Xb, x0, y0, z0);
    float v001 = fetchpad(Xb, x0, y0, z1);
    float v010 = fetchpad(Xb, x0, y1, z0);
    float v011 = fetchpad(Xb, x0, y1, z1);
    float v100 = fetchpad(Xb, x1, y0, z0);
    float v101 = fetchpad(Xb, x1, y0, z1);
    float v110 = fetchpad(Xb, x1, y1, z0);
    float v111 = fetchpad(Xb, x1, y1, z1);
    float c00 = v000 + (v001 - v000) * dz;
    float c01 = v010 + (v011 - v010) * dz;
    float c10 = v100 + (v101 - v100) * dz;
    float c11 = v110 + (v111 - v110) * dz;
    float c0 = c00 + (c01 - c00) * dy;
    float c1 = c10 + (c11 - c10) * dy;
    return c0 + (c1 - c0) * dx;
}

// ====== shared 2D-FFT pipeline (pass1 row/W, pass2 transposed/H) ======
// tile column swizzle: column c of row h stored at (c + 7h)&63  -> CF both ways
__device__ __forceinline__ int swz(int c, int h) { return (c + 7 * h) & 63; }

// ---------------- K2a: warp(X)+sign + 2D FFT(W,H) -> g_FX ----------------
__global__ void __launch_bounds__(512) k_fwd_x(const float* __restrict__ X) {
    __shared__ float2 tile[64 * P2];
    const int b = blockIdx.x >> 6, d = blockIdx.x & 63;
    const float* A = g_AX[b];
    const float* Xb = X + b * VOL;
    const float gx = (float)(d + 1) * (2.0f / 65.0f) - 1.0f;

    // pass 1: row FFT along W. thread (r=row h, j)
    {
        const int r = threadIdx.x >> 3, j = threadIdx.x & 7;
        const float gy = (float)(r + 1) * (2.0f / 65.0f) - 1.0f;
        float2 v[8];
#pragma unroll
        for (int m = 0; m < 8; m++) {
            const int w = j + 8 * m;
            const float gz = (float)(w + 1) * (2.0f / 65.0f) - 1.0f;
            float val = sampleX(Xb, A, gx, gy, gz);
            if ((d + r + w) & 1) val = -val;
            v[m] = make_float2(val, 0.f);
        }
        fft64_row<false>(tile + r * P2, j, v);
#pragma unroll
        for (int k = 0; k < 8; k++) tile[r * P2 + swz(j + 8 * k, r)] = v[k];
    }
    __syncthreads();
    // pass 2: column FFT along H, transposed mapping. thread (g=kw, jj)
    {
        const int g = threadIdx.x & 63, jj = threadIdx.x >> 6;
        float2 v[8];
#pragma unroll
        for (int m = 0; m < 8; m++) {
            const int h = jj + 8 * m;
            v[m] = tile[h * P2 + swz(g, h)];
        }
        fft64_T<false>(tile, jj, g, v);
        float2* dst = g_FX + b * VOL + d * 4096;
#pragma unroll
        for (int k = 0; k < 8; k++) dst[(jj + 8 * k) * 64 + g] = v[k];  // coalesced
    }
}

// ---------------- K2b: sign + 2D FFT(W,H) of Y -> g_FY ----------------
__global__ void __launch_bounds__(512) k_fwd_y(const float* __restrict__ Y) {
    __shared__ float2 tile[64 * P2];
    const int b = blockIdx.x >> 6, d = blockIdx.x & 63;
    const float* Yb = Y + b * VOL + d * 4096;
    {
        const int r = threadIdx.x >> 3, j = threadIdx.x & 7;
        float2 v[8];
#pragma unroll
        for (int m = 0; m < 8; m++) {
            const int w = j + 8 * m;
            float val = Yb[r * 64 + w];
            if ((d + r + w) & 1) val = -val;
            v[m] = make_float2(val, 0.f);
        }
        fft64_row<false>(tile + r * P2, j, v);
#pragma unroll
        for (int k = 0; k < 8; k++) tile[r * P2 + swz(j + 8 * k, r)] = v[k];
    }
    __syncthreads();
    {
        const int g = threadIdx.x & 63, jj = threadIdx.x >> 6;
        float2 v[8];
#pragma unroll
        for (int m = 0; m < 8; m++) {
            const int h = jj + 8 * m;
            v[m] = tile[h * P2 + swz(g, h)];
        }
        fft64_T<false>(tile, jj, g, v);
        float2* dst = g_FY + b * VOL + d * 4096;
#pragma unroll
        for (int k = 0; k < 8; k++) dst[(jj + 8 * k) * 64 + g] = v[k];  // coalesced
    }
}

// ---------------- K3: fused fwd-D(FX), fwd-D(FY), combine, inv-D ------------
// Transposed mapping throughout: all global accesses 256B-contiguous per instr.
__global__ void __launch_bounds__(512, 2) k_mid(const float* __restrict__ outp) {
    __shared__ float2 scr[64 * P2];
    const int b = blockIdx.x >> 6, h = blockIdx.x & 63;
    const int g = threadIdx.x & 63, jj = threadIdx.x >> 6;
    const int base = b * VOL + h * 64 + g;     // + d*4096

    float2 a[8], v[8];
#pragma unroll
    for (int m = 0; m < 8; m++) a[m] = g_FX[base + (jj + 8 * m) * 4096];
    fft64_T<false>(scr, jj, g, a);             // FXhat[kd = jj+8k]
#pragma unroll
    for (int m = 0; m < 8; m++) v[m] = g_FY[base + (jj + 8 * m) * 4096];
    fft64_T<false>(scr, jj, g, v);             // FYhat[kd = jj+8k]

    const float* M1 = outp + TOT;
    const float* M2 = outp + 2 * TOT;
#pragma unroll
    for (int k = 0; k < 8; k++) {
        const int kd = jj + 8 * k;
        const int off = b * VOL + kd * 4096 + h * 64 + g;
        const float m1v = __ldg(M1 + off);     // coalesced 128B
        const float m2v = __ldg(M2 + off);
        const float s = ((kd + h + g) & 1) ? -1.0f : 1.0f;
        v[k] = make_float2((a[k].x * m1v + v[k].x * m2v) * s,
                           (a[k].y * m1v + v[k].y * m2v) * s);
    }
    fft64_T<true>(scr, jj, g, v);              // inverse along D
#pragma unroll
    for (int k = 0; k < 8; k++) g_FX[base + (jj + 8 * k) * 4096] = v[k];  // coalesced
}

// ---------------- K4: inverse FFT along H (transposed) then W + real --------
__global__ void __launch_bounds__(512) k_inv_hw(float* __restrict__ out) {
    __shared__ float2 tile[64 * P2];
    const int b = blockIdx.x >> 6, d = blockIdx.x & 63;
    const float2* gsl = g_FX + b * VOL + d * 4096;
    // pass 1: inverse along H, transposed. thread (g=kw, jj)
    {
        const int g = threadIdx.x & 63, jj = threadIdx.x >> 6;
        float2 v[8];
#pragma unroll
        for (int m = 0; m < 8; m++) v[m] = gsl[(jj + 8 * m) * 64 + g];  // coalesced
        fft64_T<true>(tile, jj, g, v);
        __syncthreads();           // scr readers done before tile reuse
#pragma unroll
        for (int k = 0; k < 8; k++) {
            const int hh = jj + 8 * k;
            tile[hh * P2 + swz(g, hh)] = v[k];
        }
    }
    __syncthreads();
    // pass 2: inverse along W, row mode. thread (r=row h, j)
    {
        const int r = threadIdx.x >> 3, j = threadIdx.x & 7;
        float2 v[8];
#pragma unroll
        for (int m = 0; m < 8; m++) v[m] = tile[r * P2 + swz(j + 8 * m, r)];
        fft64_row<true>(tile + r * P2, j, v);
        float* dst = out + b * VOL + d * 4096 + r * 64;
        const float sc = 1.0f / (float)VOL;
#pragma unroll
        for (int k = 0; k < 8; k++) dst[j + 8 * k] = v[k].x * sc;   // 32B runs
    }
}

// ---------------- launch ----------------
extern "C" void kernel_launch(void* const* d_in, const int* in_sizes, int n_in,
                              void* d_out, int out_size) {
    const float* X     = (const float*)d_in[0];
    const float* Y     = (const float*)d_in[1];
    const float* m1    = (const float*)d_in[2];
    const float* m2    = (const float*)d_in[3];
    const float* theta = (const float*)d_in[4];
    float* out = (float*)d_out;

    k_setup<<<1, 32>>>(theta);
    k_warp_masks<<<TOT / 256, 256>>>(m1, m2, out);
    k_fwd_x<<<NB * 64, 512>>>(X);
    k_fwd_y<<<NB * 64, 512>>>(Y);
    k_mid<<<NB * 64, 512>>>(out);
    k_inv_hw<<<NB * 64, 512>>>(out);
}